// round 7
// baseline (speedup 1.0000x reference)
#include <cuda_runtime.h>
#include <math.h>

// Problem constants
#define NS      262144
#define KC      512
#define DEPTH   128          // 2*D
#define HALF_D  64
#define BM      128          // samples per block
#define BETA_C  0.25f
#define DECAY_C 0.99f
#define OMD_C   0.01f
#define EPS_C   1e-5f

// Output layout (float32, concatenated in reference return order)
static const size_t OFF_ZQR  = 0;               // N*D = 16777216
static const size_t OFF_ZQI  = 16777216;        // N*D
static const size_t OFF_LOSS = 33554432;        // N
static const size_t OFF_IDX  = 33816576;        // N
static const size_t OFF_ENT  = 34078720;        // 1
static const size_t OFF_EMBW = 34078721;        // K*2D = 65536
static const size_t OFF_CLUS = 34144257;        // K
static const size_t OFF_EMAW = 34144769;        // K*2D
// total 34210305

// Scratch (device globals; no allocation allowed)
__device__ __align__(16) float g_dw[KC * DEPTH];
__device__ float g_ntotal[KC];
__device__ float g_ysq[KC];
__device__ float g_cs[KC];

// ---------------- packed f32x2 helpers (Blackwell FFMA2) ----------------
// Per-lane IEEE RN FMA — bit-identical to a scalar FFMA chain (and to NEON
// vfmaq lanes in Eigen's gebp microkernel), lanes are independent accumulators.
__device__ __forceinline__ unsigned long long fma2(unsigned long long a,
                                                   unsigned long long b,
                                                   unsigned long long c) {
    unsigned long long d;
    asm("fma.rn.f32x2 %0, %1, %2, %3;" : "=l"(d) : "l"(a), "l"(b), "l"(c));
    return d;
}
__device__ __forceinline__ unsigned long long dup2(float x) {
    unsigned long long d;
    asm("mov.b64 %0, {%1, %1};" : "=l"(d) : "r"(__float_as_uint(x)));
    return d;
}
__device__ __forceinline__ void unpack2(unsigned long long p, float& lo, float& hi) {
    unsigned int a, b;
    asm("mov.b64 {%0, %1}, %2;" : "=r"(a), "=r"(b) : "l"(p));
    lo = __uint_as_float(a);
    hi = __uint_as_float(b);
}

// ---------------- kernel 1: zero scratch + y_sq[k] ------------------------
// y_sq rounding error (~1e-11) is absorbed by the ulp(128)=1.5e-5 grid of the
// final dist, so a warp-shuffle order is fine here.
__global__ void k_prep(const float* __restrict__ emb) {
    int gt   = blockIdx.x * blockDim.x + threadIdx.x;
    int row  = gt >> 5;
    int lane = gt & 31;
    if (row >= KC) return;
    float s = 0.0f;
    #pragma unroll
    for (int j = lane; j < DEPTH; j += 32) {
        float v = emb[(size_t)row * DEPTH + j];
        s = __fadd_rn(s, __fmul_rn(v, v));
        g_dw[(size_t)row * DEPTH + j] = 0.0f;
    }
    #pragma unroll
    for (int o = 16; o > 0; o >>= 1)
        s = __fadd_rn(s, __shfl_down_sync(0xffffffffu, s, o));
    if (lane == 0) {
        g_ysq[row]    = s;
        g_ntotal[row] = 0.0f;
    }
}

// ---------------- kernel 2: main fused GEMM + argmin + outputs + segment sums ----
// smem layout (floats):
#define AS_OFF   0            // As[128][132]  z tile, depth-major
#define BS_OFF   16896        // Bs[128][132]  emb tile, depth-major (reused later)
#define XSQ_OFF  33792        // x_sq[128]
#define YSQ_OFF  33920        // y_sq chunk [128]
#define BIDX_OFF 34048        // final best idx [128]
#define SMEM_FLOATS 34176
#define SMEM_BYTES  (SMEM_FLOATS * 4)

__global__ __launch_bounds__(256, 1)
void k_main(const float* __restrict__ zr, const float* __restrict__ zi,
            const float* __restrict__ emb, float* __restrict__ out) {
    extern __shared__ float sm[];
    float* As   = sm + AS_OFF;
    float* Bs   = sm + BS_OFF;
    float* XSQ  = sm + XSQ_OFF;
    float* YSQ  = sm + YSQ_OFF;
    int*   BIDX = (int*)(sm + BIDX_OFF);
    // reduction scratch + transpose reuse the Bs region
    float* rV = Bs;                  // [128][16]
    int*   rI = (int*)(Bs + 2048);   // [128][16]
    float* Tz = Bs;                  // [128][128] sample-major z (later)

    const int tid  = threadIdx.x;
    const int row0 = blockIdx.x * BM;

    // --- load z tile (depth-major: As[d][m], stride 132) ---
    for (int e = tid; e < BM * HALF_D; e += 256) {
        int m = e >> 6, d = e & 63;
        As[d * 132 + m] = zr[(size_t)(row0 + m) * HALF_D + d];
    }
    for (int e = tid; e < BM * HALF_D; e += 256) {
        int m = e >> 6, d = e & 63;
        As[(HALF_D + d) * 132 + m] = zi[(size_t)(row0 + m) * HALF_D + d];
    }
    __syncthreads();

    // --- x_sq per sample: STRICTLY SEQUENTIAL k=0..127, separate mul+add
    //     roundings (replicates XLA CPU's naive fused square+reduce loop).
    //     This value's rounding is at the scale of ulp(dist) and decides
    //     quantized-argmin near-ties, so the order is load-bearing. ---
    if (tid < BM) {
        float s = 0.0f;
        for (int k = 0; k < DEPTH; k++) {
            float v = As[k * 132 + tid];
            s = __fadd_rn(s, __fmul_rn(v, v));
        }
        XSQ[tid] = s;
    }

    const int tx = tid & 15;   // codeword dim: 16 x 8
    const int ty = tid >> 4;   // sample dim:   16 x 8
    float bval[8];
    int   bidx[8];
    #pragma unroll
    for (int i = 0; i < 8; i++) { bval[i] = 3.4e38f; bidx[i] = 0; }

    const float* Arow = As + ty * 8;
    const float* Brow = Bs + tx * 8;

    for (int c = 0; c < 4; c++) {
        __syncthreads();
        // load emb chunk transposed: Bs[k][n] = emb[(c*128+n)*128 + k]
        for (int e = tid; e < 128 * 128; e += 256) {
            int n = e >> 7, k = e & 127;
            Bs[k * 132 + n] = emb[(size_t)(c * 128 + n) * DEPTH + k];
        }
        if (tid < 128) YSQ[tid] = g_ysq[c * 128 + tid];
        __syncthreads();

        unsigned long long acc[8][4];
        #pragma unroll
        for (int i = 0; i < 8; i++)
            #pragma unroll
            for (int j = 0; j < 4; j++) acc[i][j] = 0ull;

        // Sequential-k FMA chain, one accumulator per (m,n) — bit-identical
        // to Eigen gebp's per-element NEON FMA chain over k ascending.
        #pragma unroll 4
        for (int kk = 0; kk < DEPTH; kk++) {
            const float4* ap4 = (const float4*)(Arow + kk * 132);
            float4 a0 = ap4[0];
            float4 a1 = ap4[1];
            const unsigned long long* bp = (const unsigned long long*)(Brow + kk * 132);
            unsigned long long b0 = bp[0], b1 = bp[1], b2 = bp[2], b3 = bp[3];
            unsigned long long ad[8];
            ad[0] = dup2(a0.x); ad[1] = dup2(a0.y); ad[2] = dup2(a0.z); ad[3] = dup2(a0.w);
            ad[4] = dup2(a1.x); ad[5] = dup2(a1.y); ad[6] = dup2(a1.z); ad[7] = dup2(a1.w);
            #pragma unroll
            for (int i = 0; i < 8; i++) {
                acc[i][0] = fma2(ad[i], b0, acc[i][0]);
                acc[i][1] = fma2(ad[i], b1, acc[i][1]);
                acc[i][2] = fma2(ad[i], b2, acc[i][2]);
                acc[i][3] = fma2(ad[i], b3, acc[i][3]);
            }
        }

        // chunk epilogue: dist = fl(fl(x_sq + y_sq) - 2*dot), EXACTLY the
        // reference's op structure (2*dot exact, one rounded add each step).
        float xs = XSQ[ty * 8 + 0];   // placeholder init, set per i below
        #pragma unroll
        for (int i = 0; i < 8; i++) {
            xs = XSQ[ty * 8 + i];
            #pragma unroll
            for (int j = 0; j < 4; j++) {
                float lo, hi;
                unpack2(acc[i][j], lo, hi);
                int n0 = c * 128 + tx * 8 + 2 * j;
                float t0 = __fadd_rn(xs, YSQ[tx * 8 + 2 * j]);
                float t1 = __fadd_rn(xs, YSQ[tx * 8 + 2 * j + 1]);
                float s0 = __fadd_rn(t0, __fmul_rn(-2.0f, lo));
                float s1 = __fadd_rn(t1, __fmul_rn(-2.0f, hi));
                if (s0 < bval[i]) { bval[i] = s0; bidx[i] = n0; }
                if (s1 < bval[i]) { bval[i] = s1; bidx[i] = n0 + 1; }
            }
        }
    }
    __syncthreads();   // all threads done reading Bs before reuse

    // --- cross-tx argmin reduction (Bs region reused); first-min-index
    //     semantics exactly like jnp.argmin ---
    #pragma unroll
    for (int i = 0; i < 8; i++) {
        int m = ty * 8 + i;
        rV[m * 16 + tx] = bval[i];
        rI[m * 16 + tx] = bidx[i];
    }
    __syncthreads();
    if (tid < BM) {
        float bv = 3.4e38f;
        int   bi = 0x7fffffff;
        #pragma unroll
        for (int t = 0; t < 16; t++) {
            float v = rV[tid * 16 + t];
            int  ix = rI[tid * 16 + t];
            if (v < bv || (v == bv && ix < bi)) { bv = v; bi = ix; }
        }
        BIDX[tid] = bi;
        out[OFF_IDX + row0 + tid]  = (float)bi;
        // loss = BETA * dist/128; dist==||z-q||^2 to ~1e-5 abs -> ~4e-7 rel
        out[OFF_LOSS + row0 + tid] = __fmul_rn(BETA_C, __fmul_rn(bv, (1.0f / 128.0f)));
        atomicAdd(&g_ntotal[bi], 1.0f);
    }
    __syncthreads();

    // --- transpose z into sample-major Tz[m][d] (stride 128) ---
    for (int e = tid; e < BM * DEPTH; e += 256) {
        int m = e >> 7, d = e & 127;
        Tz[m * 128 + d] = As[d * 132 + m];
    }
    __syncthreads();

    // --- zq gather + straight-through write + dw vector segment-sum ---
    for (int e = tid; e < BM * 32; e += 256) {
        int m = e >> 5;
        int d = (e & 31) * 4;
        float4 zv = *(const float4*)&Tz[m * 128 + d];
        int ix = BIDX[m];
        float4 qv = *(const float4*)&emb[(size_t)ix * DEPTH + d];
        float4 o;   // reference: z + fl(q - z), each op rounded once
        o.x = __fadd_rn(zv.x, __fsub_rn(qv.x, zv.x));
        o.y = __fadd_rn(zv.y, __fsub_rn(qv.y, zv.y));
        o.z = __fadd_rn(zv.z, __fsub_rn(qv.z, zv.z));
        o.w = __fadd_rn(zv.w, __fsub_rn(qv.w, zv.w));
        size_t gi = (size_t)(row0 + m);
        if (d < HALF_D)
            *(float4*)&out[OFF_ZQR + gi * HALF_D + d] = o;
        else
            *(float4*)&out[OFF_ZQI + gi * HALF_D + (d - HALF_D)] = o;
        // dw segment-sum: vectorized fp32 reduction (sm_90+ intrinsic -> REDG.128)
        atomicAdd((float4*)&g_dw[ix * DEPTH + d], zv);
    }
}

// ---------------- kernel 3a: cluster EMA, tot, entropy ----------------
__global__ void k_final_a(const float* __restrict__ ecs, float* __restrict__ out) {
    __shared__ float red[KC];
    __shared__ float red2[KC];
    int t = threadIdx.x;
    float nt = g_ntotal[t];
    float nc = __fadd_rn(__fmul_rn(ecs[t], DECAY_C), __fmul_rn(OMD_C, nt));
    float p  = __fmul_rn(nt, (1.0f / (float)NS));
    red[t]  = nc;
    red2[t] = -__fmul_rn(p, logf(__fadd_rn(p, 1e-10f)));
    __syncthreads();
    for (int s = KC / 2; s > 0; s >>= 1) {
        if (t < s) { red[t] += red[t + s]; red2[t] += red2[t + s]; }
        __syncthreads();
    }
    float tot = red[0];
    out[OFF_CLUS + t] = nc;
    g_cs[t] = __fmul_rn(__fdiv_rn(__fadd_rn(nc, EPS_C),
                                  __fadd_rn(tot, __fmul_rn((float)KC, EPS_C))), tot);
    if (t == 0) out[OFF_ENT] = __fdiv_rn(red2[0], logf(512.0f));
}

// ---------------- kernel 3b: ema_w / emb_w update ----------------
__global__ void k_final_b(const float* __restrict__ emaw, float* __restrict__ out) {
    int e = blockIdx.x * blockDim.x + threadIdx.x;   // 65536 threads
    int k = e >> 7;
    float ew = __fadd_rn(__fmul_rn(emaw[e], DECAY_C), __fmul_rn(OMD_C, g_dw[e]));
    out[OFF_EMAW + e] = ew;
    out[OFF_EMBW + e] = __fdiv_rn(ew, g_cs[k]);
}

// ---------------- launch ----------------
extern "C" void kernel_launch(void* const* d_in, const int* in_sizes, int n_in,
                              void* d_out, int out_size) {
    const float* zr   = (const float*)d_in[0];
    const float* zi   = (const float*)d_in[1];
    const float* emb  = (const float*)d_in[2];
    const float* ecs  = (const float*)d_in[3];
    const float* emaw = (const float*)d_in[4];
    float* out = (float*)d_out;

    cudaFuncSetAttribute(k_main, cudaFuncAttributeMaxDynamicSharedMemorySize, SMEM_BYTES);

    k_prep<<<64, 256>>>(emb);
    k_main<<<NS / BM, 256, SMEM_BYTES>>>(zr, zi, emb, out);
    k_final_a<<<1, KC>>>(ecs, out);
    k_final_b<<<KC * DEPTH / 256, 256>>>(emaw, out);
}

// round 8
// speedup vs baseline: 1.0503x; 1.0503x over previous
#include <cuda_runtime.h>
#include <math.h>

// Problem constants
#define NS      262144
#define KC      512
#define DEPTH   128          // 2*D
#define HALF_D  64
#define BM      128          // samples per block
#define BETA_C  0.25f
#define DECAY_C 0.99f
#define OMD_C   0.01f
#define EPS_C   1e-5f

// Output layout (float32, concatenated in reference return order)
static const size_t OFF_ZQR  = 0;               // N*D = 16777216
static const size_t OFF_ZQI  = 16777216;        // N*D
static const size_t OFF_LOSS = 33554432;        // N
static const size_t OFF_IDX  = 33816576;        // N
static const size_t OFF_ENT  = 34078720;        // 1
static const size_t OFF_EMBW = 34078721;        // K*2D = 65536
static const size_t OFF_CLUS = 34144257;        // K
static const size_t OFF_EMAW = 34144769;        // K*2D
// total 34210305

// Scratch (device globals; no allocation allowed)
__device__ __align__(16) float g_dw[KC * DEPTH];
__device__ float g_ntotal[KC];
__device__ float g_ysq[KC];
__device__ float g_cs[KC];

// ---------------- packed f32x2 helpers (Blackwell FFMA2) ----------------
// Per-lane IEEE RN FMA — bit-identical to a scalar FFMA chain; lanes are
// independent accumulators. Chain order (k ascending) is load-bearing for
// the bit-exact argmin match with the reference; do not reorder.
__device__ __forceinline__ unsigned long long fma2(unsigned long long a,
                                                   unsigned long long b,
                                                   unsigned long long c) {
    unsigned long long d;
    asm("fma.rn.f32x2 %0, %1, %2, %3;" : "=l"(d) : "l"(a), "l"(b), "l"(c));
    return d;
}
__device__ __forceinline__ unsigned long long dup2(float x) {
    unsigned long long d;
    asm("mov.b64 %0, {%1, %1};" : "=l"(d) : "r"(__float_as_uint(x)));
    return d;
}
__device__ __forceinline__ void unpack2(unsigned long long p, float& lo, float& hi) {
    unsigned int a, b;
    asm("mov.b64 {%0, %1}, %2;" : "=r"(a), "=r"(b) : "l"(p));
    lo = __uint_as_float(a);
    hi = __uint_as_float(b);
}

// ---------------- kernel 1: zero scratch + y_sq[k] ------------------------
__global__ void k_prep(const float* __restrict__ emb) {
    int gt   = blockIdx.x * blockDim.x + threadIdx.x;
    int row  = gt >> 5;
    int lane = gt & 31;
    if (row >= KC) return;
    float s = 0.0f;
    #pragma unroll
    for (int j = lane; j < DEPTH; j += 32) {
        float v = emb[(size_t)row * DEPTH + j];
        s = __fadd_rn(s, __fmul_rn(v, v));
        g_dw[(size_t)row * DEPTH + j] = 0.0f;
    }
    #pragma unroll
    for (int o = 16; o > 0; o >>= 1)
        s = __fadd_rn(s, __shfl_down_sync(0xffffffffu, s, o));
    if (lane == 0) {
        g_ysq[row]    = s;
        g_ntotal[row] = 0.0f;
    }
}

// ---------------- kernel 2: main fused GEMM + argmin + outputs + segment sums ----
// smem layout (floats):
//   As: [128 depth][132]           z tile, depth-major          16896 floats
//   Bs: [128 depth][196]           emb tile, CONFLICT-FREE      25088 floats
//       per depth row: 16 groups of (8 data floats + 4 pad) -> thread tx
//       reads its 8 codewords contiguously at byte offset tx*48; 48*t mod 128
//       covers all 8 quad positions (gcd(48,128)=16) -> 2-way (broadcast) =
//       distinct-byte floor, no bank conflicts.
#define AS_OFF   0
#define BS_OFF   16896
#define XSQ_OFF  41984        // x_sq[128]
#define YSQ_OFF  42112        // y_sq chunk [128]
#define BIDX_OFF 42240        // final best idx [128]
#define SMEM_FLOATS 42368
#define SMEM_BYTES  (SMEM_FLOATS * 4)

__global__ __launch_bounds__(256, 1)
void k_main(const float* __restrict__ zr, const float* __restrict__ zi,
            const float* __restrict__ emb, float* __restrict__ out) {
    extern __shared__ float sm[];
    float* As   = sm + AS_OFF;
    float* Bs   = sm + BS_OFF;
    float* XSQ  = sm + XSQ_OFF;
    float* YSQ  = sm + YSQ_OFF;
    int*   BIDX = (int*)(sm + BIDX_OFF);
    // reduction scratch + transpose reuse the Bs region
    float* rV = Bs;                  // [128][16]
    int*   rI = (int*)(Bs + 2048);   // [128][16]
    float* Tz = Bs;                  // [128][128] sample-major z (later)

    const int tid  = threadIdx.x;
    const int row0 = blockIdx.x * BM;

    // --- load z tile (depth-major: As[d][m], stride 132) ---
    for (int e = tid; e < BM * HALF_D; e += 256) {
        int m = e >> 6, d = e & 63;
        As[d * 132 + m] = zr[(size_t)(row0 + m) * HALF_D + d];
    }
    for (int e = tid; e < BM * HALF_D; e += 256) {
        int m = e >> 6, d = e & 63;
        As[(HALF_D + d) * 132 + m] = zi[(size_t)(row0 + m) * HALF_D + d];
    }
    __syncthreads();

    // --- x_sq per sample: STRICTLY SEQUENTIAL k=0..127, separate mul+add
    //     roundings. Order is load-bearing for the bit-exact argmin. ---
    if (tid < BM) {
        float s = 0.0f;
        for (int k = 0; k < DEPTH; k++) {
            float v = As[k * 132 + tid];
            s = __fadd_rn(s, __fmul_rn(v, v));
        }
        XSQ[tid] = s;
    }

    const int tx = tid & 15;   // codeword dim: 16 x 8
    const int ty = tid >> 4;   // sample dim:   16 x 8
    float bval[8];
    int   bidx[8];
    #pragma unroll
    for (int i = 0; i < 8; i++) { bval[i] = 3.4e38f; bidx[i] = 0; }

    const float* Arow = As + ty * 8;
    const float* Brow = Bs + tx * 12;     // 8 data floats + 4 pad per thread

    for (int c = 0; c < 4; c++) {
        __syncthreads();
        // load emb chunk: Bs[k][group(n)] = emb[(c*128+n)*128 + k]
        // gmem coalesced over k; STS 4-way (noise vs mainloop)
        for (int e = tid; e < 128 * 128; e += 256) {
            int n = e >> 7, k = e & 127;
            Bs[k * 196 + (n >> 3) * 12 + (n & 7)] = emb[(size_t)(c * 128 + n) * DEPTH + k];
        }
        if (tid < 128) YSQ[tid] = g_ysq[c * 128 + tid];
        __syncthreads();

        unsigned long long acc[8][4];
        #pragma unroll
        for (int i = 0; i < 8; i++)
            #pragma unroll
            for (int j = 0; j < 4; j++) acc[i][j] = 0ull;

        // Sequential-k FMA chain, one accumulator per (m,n) — bit-identical
        // to the reference's per-element FMA chain over k ascending.
        #pragma unroll 4
        for (int kk = 0; kk < DEPTH; kk++) {
            const float4* ap4 = (const float4*)(Arow + kk * 132);
            float4 a0 = ap4[0];
            float4 a1 = ap4[1];
            const ulonglong2* bp = (const ulonglong2*)(Brow + kk * 196);
            ulonglong2 B0 = bp[0];        // codewords 0..3 (2 ull pairs)
            ulonglong2 B1 = bp[1];        // codewords 4..7
            unsigned long long ad[8];
            ad[0] = dup2(a0.x); ad[1] = dup2(a0.y); ad[2] = dup2(a0.z); ad[3] = dup2(a0.w);
            ad[4] = dup2(a1.x); ad[5] = dup2(a1.y); ad[6] = dup2(a1.z); ad[7] = dup2(a1.w);
            #pragma unroll
            for (int i = 0; i < 8; i++) {
                acc[i][0] = fma2(ad[i], B0.x, acc[i][0]);
                acc[i][1] = fma2(ad[i], B0.y, acc[i][1]);
                acc[i][2] = fma2(ad[i], B1.x, acc[i][2]);
                acc[i][3] = fma2(ad[i], B1.y, acc[i][3]);
            }
        }

        // chunk epilogue: dist = fl(fl(x_sq + y_sq) - 2*dot), EXACTLY the
        // reference's op structure (2*dot exact, one rounded add each step).
        #pragma unroll
        for (int i = 0; i < 8; i++) {
            float xs = XSQ[ty * 8 + i];
            #pragma unroll
            for (int j = 0; j < 4; j++) {
                float lo, hi;
                unpack2(acc[i][j], lo, hi);
                int n0 = c * 128 + tx * 8 + 2 * j;
                float t0 = __fadd_rn(xs, YSQ[tx * 8 + 2 * j]);
                float t1 = __fadd_rn(xs, YSQ[tx * 8 + 2 * j + 1]);
                float s0 = __fadd_rn(t0, __fmul_rn(-2.0f, lo));
                float s1 = __fadd_rn(t1, __fmul_rn(-2.0f, hi));
                if (s0 < bval[i]) { bval[i] = s0; bidx[i] = n0; }
                if (s1 < bval[i]) { bval[i] = s1; bidx[i] = n0 + 1; }
            }
        }
    }
    __syncthreads();   // all threads done reading Bs before reuse

    // --- cross-tx argmin reduction (Bs region reused); first-min-index
    //     semantics exactly like jnp.argmin ---
    #pragma unroll
    for (int i = 0; i < 8; i++) {
        int m = ty * 8 + i;
        rV[m * 16 + tx] = bval[i];
        rI[m * 16 + tx] = bidx[i];
    }
    __syncthreads();
    if (tid < BM) {
        float bv = 3.4e38f;
        int   bi = 0x7fffffff;
        #pragma unroll
        for (int t = 0; t < 16; t++) {
            float v = rV[tid * 16 + t];
            int  ix = rI[tid * 16 + t];
            if (v < bv || (v == bv && ix < bi)) { bv = v; bi = ix; }
        }
        BIDX[tid] = bi;
        out[OFF_IDX + row0 + tid]  = (float)bi;
        out[OFF_LOSS + row0 + tid] = __fmul_rn(BETA_C, __fmul_rn(bv, (1.0f / 128.0f)));
        atomicAdd(&g_ntotal[bi], 1.0f);
    }
    __syncthreads();

    // --- transpose z into sample-major Tz[m][d] (stride 128) ---
    for (int e = tid; e < BM * DEPTH; e += 256) {
        int m = e >> 7, d = e & 127;
        Tz[m * 128 + d] = As[d * 132 + m];
    }
    __syncthreads();

    // --- zq gather + straight-through write + dw vector segment-sum ---
    for (int e = tid; e < BM * 32; e += 256) {
        int m = e >> 5;
        int d = (e & 31) * 4;
        float4 zv = *(const float4*)&Tz[m * 128 + d];
        int ix = BIDX[m];
        float4 qv = *(const float4*)&emb[(size_t)ix * DEPTH + d];
        float4 o;   // reference: z + fl(q - z), each op rounded once
        o.x = __fadd_rn(zv.x, __fsub_rn(qv.x, zv.x));
        o.y = __fadd_rn(zv.y, __fsub_rn(qv.y, zv.y));
        o.z = __fadd_rn(zv.z, __fsub_rn(qv.z, zv.z));
        o.w = __fadd_rn(zv.w, __fsub_rn(qv.w, zv.w));
        size_t gi = (size_t)(row0 + m);
        if (d < HALF_D)
            *(float4*)&out[OFF_ZQR + gi * HALF_D + d] = o;
        else
            *(float4*)&out[OFF_ZQI + gi * HALF_D + (d - HALF_D)] = o;
        // dw segment-sum: vectorized fp32 reduction (sm_90+ intrinsic -> REDG.128)
        atomicAdd((float4*)&g_dw[ix * DEPTH + d], zv);
    }
}

// ---------------- kernel 3a: cluster EMA, tot, entropy ----------------
__global__ void k_final_a(const float* __restrict__ ecs, float* __restrict__ out) {
    __shared__ float red[KC];
    __shared__ float red2[KC];
    int t = threadIdx.x;
    float nt = g_ntotal[t];
    float nc = __fadd_rn(__fmul_rn(ecs[t], DECAY_C), __fmul_rn(OMD_C, nt));
    float p  = __fmul_rn(nt, (1.0f / (float)NS));
    red[t]  = nc;
    red2[t] = -__fmul_rn(p, logf(__fadd_rn(p, 1e-10f)));
    __syncthreads();
    for (int s = KC / 2; s > 0; s >>= 1) {
        if (t < s) { red[t] += red[t + s]; red2[t] += red2[t + s]; }
        __syncthreads();
    }
    float tot = red[0];
    out[OFF_CLUS + t] = nc;
    g_cs[t] = __fmul_rn(__fdiv_rn(__fadd_rn(nc, EPS_C),
                                  __fadd_rn(tot, __fmul_rn((float)KC, EPS_C))), tot);
    if (t == 0) out[OFF_ENT] = __fdiv_rn(red2[0], logf(512.0f));
}

// ---------------- kernel 3b: ema_w / emb_w update ----------------
__global__ void k_final_b(const float* __restrict__ emaw, float* __restrict__ out) {
    int e = blockIdx.x * blockDim.x + threadIdx.x;   // 65536 threads
    int k = e >> 7;
    float ew = __fadd_rn(__fmul_rn(emaw[e], DECAY_C), __fmul_rn(OMD_C, g_dw[e]));
    out[OFF_EMAW + e] = ew;
    out[OFF_EMBW + e] = __fdiv_rn(ew, g_cs[k]);
}

// ---------------- launch ----------------
extern "C" void kernel_launch(void* const* d_in, const int* in_sizes, int n_in,
                              void* d_out, int out_size) {
    const float* zr   = (const float*)d_in[0];
    const float* zi   = (const float*)d_in[1];
    const float* emb  = (const float*)d_in[2];
    const float* ecs  = (const float*)d_in[3];
    const float* emaw = (const float*)d_in[4];
    float* out = (float*)d_out;

    cudaFuncSetAttribute(k_main, cudaFuncAttributeMaxDynamicSharedMemorySize, SMEM_BYTES);

    k_prep<<<64, 256>>>(emb);
    k_main<<<NS / BM, 256, SMEM_BYTES>>>(zr, zi, emb, out);
    k_final_a<<<1, KC>>>(ecs, out);
    k_final_b<<<KC * DEPTH / 256, 256>>>(emaw, out);
}